// round 1
// baseline (speedup 1.0000x reference)
#include <cuda_runtime.h>
#include <cstddef>

#define NBND 400001
#define NATM 100000
#define HD   300
#define AF   133
#define BF   147
#define MAXNB 6
#define NUND 200001   // undirected bonds (incl. pad row 0)

// ---------------- scratch (static device globals; no allocation allowed) ----
__device__ float g_inp [(size_t)NBND * HD];   // pre-relu input messages
__device__ float g_msgA[(size_t)NBND * HD];
__device__ float g_msgB[(size_t)NBND * HD];
__device__ float g_amsg[(size_t)NATM * HD];
__device__ float g_hid [(size_t)NATM * HD];
__device__ float g_und [(size_t)NUND * HD];
__device__ double g_sum  [2][HD];
__device__ double g_sumsq[2][HD];

// ---------------- GEMM: C[M,HD] = A[M,K] * Bw[K,HD] (+epilogues) ------------
// MODE 0: A = f_bonds (K=BF).   out = relu(acc), out2 = acc  (inp)
// MODE 1: A = m on-the-fly: amsg[b2a[r]] - msgsrc[b2revb[r]] (K=HD)
//         out = relu(inp + acc)
// MODE 2: A = concat(f_atoms, amsg) (K=AF+HD). out = relu(acc + bias)
constexpr int BM = 64, BN = 128, BK = 16;

template <int MODE>
__global__ __launch_bounds__(256) void gemm_kernel(
    const float* __restrict__ A,
    const float* __restrict__ Bw,
    const float* __restrict__ inp,
    const float* __restrict__ amsg,
    const float* __restrict__ msgsrc,
    const int*   __restrict__ b2a,
    const int*   __restrict__ b2revb,
    const float* __restrict__ bias,
    float* __restrict__ out,
    float* __restrict__ out2,
    int M, int K)
{
    __shared__ float As[BK][BM];
    __shared__ float Bs[BK][BN];
    __shared__ int sIA[BM], sIB[BM];

    const int tid = threadIdx.x;
    const int m0 = blockIdx.y * BM;
    const int n0 = blockIdx.x * BN;
    const int ty = tid >> 4, tx = tid & 15;

    if (MODE == 1) {
        if (tid < BM) {
            int r = m0 + tid;
            sIA[tid] = (r < M) ? b2a[r]    : 0;
            sIB[tid] = (r < M) ? b2revb[r] : 0;
        }
        __syncthreads();
    }

    float c[4][8];
#pragma unroll
    for (int i = 0; i < 4; i++)
#pragma unroll
        for (int j = 0; j < 8; j++) c[i][j] = 0.f;

    for (int k0 = 0; k0 < K; k0 += BK) {
        // A tile (64 x 16), transposed into As[k][m]
#pragma unroll
        for (int i = 0; i < 4; i++) {
            int e = tid + i * 256;
            int m = e >> 4, kq = e & 15;
            int r = m0 + m, kk = k0 + kq;
            float v = 0.f;
            if (r < M && kk < K) {
                if (MODE == 0)
                    v = A[(size_t)r * BF + kk];
                else if (MODE == 1)
                    v = amsg[(size_t)sIA[m] * HD + kk] - msgsrc[(size_t)sIB[m] * HD + kk];
                else
                    v = (kk < AF) ? A[(size_t)r * AF + kk]
                                  : amsg[(size_t)r * HD + (kk - AF)];
            }
            As[kq][m] = v;
        }
        // B tile (16 x 128)
#pragma unroll
        for (int i = 0; i < 8; i++) {
            int e = tid + i * 256;
            int kq = e >> 7, n = e & 127;
            int kk = k0 + kq, nn = n0 + n;
            Bs[kq][n] = (kk < K && nn < HD) ? Bw[(size_t)kk * HD + nn] : 0.f;
        }
        __syncthreads();
#pragma unroll
        for (int kq = 0; kq < BK; kq++) {
            float4 a  = *(const float4*)&As[kq][ty * 4];
            float4 b0 = *(const float4*)&Bs[kq][tx * 4];
            float4 b1 = *(const float4*)&Bs[kq][64 + tx * 4];
            float av[4] = {a.x, a.y, a.z, a.w};
            float bv[8] = {b0.x, b0.y, b0.z, b0.w, b1.x, b1.y, b1.z, b1.w};
#pragma unroll
            for (int i = 0; i < 4; i++)
#pragma unroll
                for (int j = 0; j < 8; j++) c[i][j] += av[i] * bv[j];
        }
        __syncthreads();
    }

#pragma unroll
    for (int i = 0; i < 4; i++) {
        int r = m0 + ty * 4 + i;
        if (r >= M) continue;
#pragma unroll
        for (int j = 0; j < 8; j++) {
            int n = n0 + ((j < 4) ? (tx * 4 + j) : (64 + tx * 4 + (j - 4)));
            if (n >= HD) continue;
            float v = c[i][j];
            size_t o = (size_t)r * HD + n;
            if (MODE == 0)      { out2[o] = v; out[o] = fmaxf(v, 0.f); }
            else if (MODE == 1) { out[o] = fmaxf(inp[o] + v, 0.f); }
            else                { out[o] = fmaxf(v + bias[n], 0.f); }
        }
    }
}

// ---------------- neighbor aggregation: amsg[i] = sum_j msg[a2b[i,j]] -------
__global__ void agg_kernel(const float* __restrict__ msg,
                           const int* __restrict__ a2b,
                           float* __restrict__ amsg)
{
    int idx = blockIdx.x * blockDim.x + threadIdx.x;
    if (idx >= NATM * 75) return;
    int i = idx / 75, k4 = idx % 75;
    float4 s = {0.f, 0.f, 0.f, 0.f};
#pragma unroll
    for (int j = 0; j < MAXNB; j++) {
        int b = a2b[i * MAXNB + j];
        float4 v = *(const float4*)(msg + (size_t)b * HD + k4 * 4);
        s.x += v.x; s.y += v.y; s.z += v.z; s.w += v.w;
    }
    *(float4*)(amsg + (size_t)i * HD + k4 * 4) = s;
}

// ---------------- undirected pairing ---------------------------------------
__global__ void und_kernel(const float* __restrict__ msg, float* __restrict__ und)
{
    int idx = blockIdx.x * blockDim.x + threadIdx.x;
    if (idx >= NUND * 75) return;
    int r = idx / 75, k4 = idx % 75;
    int r1 = 2 * r;
    int r2 = (r == 0) ? 0 : (2 * r - 1);
    float4 a = *(const float4*)(msg + (size_t)r1 * HD + k4 * 4);
    float4 b = *(const float4*)(msg + (size_t)r2 * HD + k4 * 4);
    float4 o;
    o.x = 0.5f * (a.x + b.x); o.y = 0.5f * (a.y + b.y);
    o.z = 0.5f * (a.z + b.z); o.w = 0.5f * (a.w + b.w);
    *(float4*)(und + (size_t)r * HD + k4 * 4) = o;
}

// ---------------- batchnorm (two-pass, fp64 accumulation) -------------------
__global__ void zero_stats()
{
    int t = blockIdx.x * blockDim.x + threadIdx.x;
    if (t < 2 * HD) {
        (&g_sum[0][0])[t]   = 0.0;
        (&g_sumsq[0][0])[t] = 0.0;
    }
}

__global__ void stats_kernel(const float* __restrict__ x, int rows,
                             double* __restrict__ sum, double* __restrict__ sumsq)
{
    int c = threadIdx.x;
    if (c >= HD) return;
    long r0 = (long)blockIdx.x * 512;
    long r1 = r0 + 512; if (r1 > rows) r1 = rows;
    double s = 0.0, s2 = 0.0;
    for (long r = r0; r < r1; r++) {
        double v = (double)x[(size_t)r * HD + c];
        s += v; s2 += v * v;
    }
    atomicAdd(&sum[c], s);
    atomicAdd(&sumsq[c], s2);
}

__global__ void norm_kernel(const float* __restrict__ x, int rows,
                            const double* __restrict__ sum,
                            const double* __restrict__ sumsq,
                            const float* __restrict__ gamma,
                            const float* __restrict__ beta,
                            float* __restrict__ out)
{
    long idx = (long)blockIdx.x * blockDim.x + threadIdx.x;
    long tot = (long)rows * HD;
    if (idx >= tot) return;
    int c = (int)(idx % HD);
    double mu  = sum[c] / rows;
    double var = sumsq[c] / rows - mu * mu;
    float sc = gamma[c] * (float)(1.0 / sqrt(var + 1e-5));
    out[idx] = (x[idx] - (float)mu) * sc + beta[c];
}

// ---------------- launch -----------------------------------------------------
extern "C" void kernel_launch(void* const* d_in, const int* in_sizes, int n_in,
                              void* d_out, int out_size)
{
    const float* f_atoms = (const float*)d_in[0];
    const float* f_bonds = (const float*)d_in[1];
    const int*   a2b     = (const int*)  d_in[2];
    const int*   b2a     = (const int*)  d_in[3];
    const int*   b2revb  = (const int*)  d_in[4];
    const float* W_i     = (const float*)d_in[5];
    const float* W_h     = (const float*)d_in[6];
    const float* W_o     = (const float*)d_in[7];
    const float* b_o     = (const float*)d_in[8];
    const float* gamma   = (const float*)d_in[9];
    const float* beta    = (const float*)d_in[10];

    float *inp, *msgA, *msgB, *amsg, *hid, *und;
    double *sum, *sumsq;
    cudaGetSymbolAddress((void**)&inp,  g_inp);
    cudaGetSymbolAddress((void**)&msgA, g_msgA);
    cudaGetSymbolAddress((void**)&msgB, g_msgB);
    cudaGetSymbolAddress((void**)&amsg, g_amsg);
    cudaGetSymbolAddress((void**)&hid,  g_hid);
    cudaGetSymbolAddress((void**)&und,  g_und);
    cudaGetSymbolAddress((void**)&sum,  g_sum);
    cudaGetSymbolAddress((void**)&sumsq,g_sumsq);

    zero_stats<<<1, 1024>>>();

    dim3 gB((HD + BN - 1) / BN, (NBND + BM - 1) / BM);   // 3 x 6251
    dim3 gO((HD + BN - 1) / BN, (NATM + BM - 1) / BM);   // 3 x 1563
    const int AGG_G = (NATM * 75 + 255) / 256;

    // inp = f_bonds @ W_i ; msgA = relu(inp)
    gemm_kernel<0><<<gB, 256>>>(f_bonds, W_i, nullptr, nullptr, nullptr,
                                nullptr, nullptr, nullptr, msgA, inp, NBND, BF);
    // depth iteration 1
    agg_kernel<<<AGG_G, 256>>>(msgA, a2b, amsg);
    gemm_kernel<1><<<gB, 256>>>(nullptr, W_h, inp, amsg, msgA,
                                b2a, b2revb, nullptr, msgB, nullptr, NBND, HD);
    // depth iteration 2
    agg_kernel<<<AGG_G, 256>>>(msgB, a2b, amsg);
    gemm_kernel<1><<<gB, 256>>>(nullptr, W_h, inp, amsg, msgB,
                                b2a, b2revb, nullptr, msgA, nullptr, NBND, HD);
    // undirected pairing from final message
    und_kernel<<<(NUND * 75 + 255) / 256, 256>>>(msgA, und);
    // final aggregation + output transform
    agg_kernel<<<AGG_G, 256>>>(msgA, a2b, amsg);
    gemm_kernel<2><<<gO, 256>>>(f_atoms, W_o, nullptr, amsg, nullptr,
                                nullptr, nullptr, b_o, hid, nullptr, NATM, AF + HD);

    // batchnorm over rows [1:]
    stats_kernel<<<(NATM - 1 + 511) / 512, 320>>>(hid + HD, NATM - 1, sum, sumsq);
    stats_kernel<<<(NUND - 1 + 511) / 512, 320>>>(und + HD, NUND - 1, sum + HD, sumsq + HD);

    float* outp = (float*)d_out;
    long nAtomOut = (long)(NATM - 1) * HD;
    long nBondOut = (long)(NUND - 1) * HD;
    norm_kernel<<<(int)((nAtomOut + 255) / 256), 256>>>(hid + HD, NATM - 1, sum, sumsq,
                                                        gamma, beta, outp);
    norm_kernel<<<(int)((nBondOut + 255) / 256), 256>>>(und + HD, NUND - 1, sum + HD, sumsq + HD,
                                                        gamma, beta, outp + nAtomOut);
}

// round 2
// speedup vs baseline: 1.7444x; 1.7444x over previous
#include <cuda_runtime.h>
#include <cstddef>

#define NBND 400001
#define NATM 100000
#define HD   300
#define AF   133
#define BF   147
#define MAXNB 6
#define NUND 200001   // undirected bonds (incl. pad row 0)

// ---------------- scratch (static device globals; no allocation allowed) ----
__device__ float g_inp [(size_t)NBND * HD];   // pre-relu input messages
__device__ float g_msgA[(size_t)NBND * HD];
__device__ float g_msgB[(size_t)NBND * HD];
__device__ float g_amsg[(size_t)NATM * HD];
__device__ float g_hid [(size_t)NATM * HD];
__device__ float g_und [(size_t)NUND * HD];
__device__ double g_sum  [2][HD];
__device__ double g_sumsq[2][HD];
__device__ float g_scale[2][HD];
__device__ float g_shift[2][HD];

// ---------------- GEMM: C[M,HD] = A[M,K] * Bw[K,HD] (+epilogues) ------------
// MODE 0: A = f_bonds (K=BF).   out = relu(acc), out2 = acc  (inp)
// MODE 1: A = amsg[b2a[r]] - msgsrc[b2revb[r]] on the fly (K=HD)
//         out = relu(inp + acc)
// MODE 2: A = concat(f_atoms, amsg) (K=AF+HD). out = relu(acc + bias)
constexpr int BM = 128, BN = 128, BK = 16;
constexpr int AP = BM + 4;   // padded As row (keeps 16B alignment, ~2-way store conflict)

template <int MODE>
__global__ __launch_bounds__(256, 2) void gemm_kernel(
    const float* __restrict__ A,
    const float* __restrict__ Bw,
    const float* __restrict__ inp,
    const float* __restrict__ amsg,
    const float* __restrict__ msgsrc,
    const int*   __restrict__ b2a,
    const int*   __restrict__ b2revb,
    const float* __restrict__ bias,
    float* __restrict__ out,
    float* __restrict__ out2,
    int M, int K)
{
    __shared__ float As[2][BK][AP];
    __shared__ float Bs[2][BK][BN];
    __shared__ int sIA[BM], sIB[BM];

    const int tid = threadIdx.x;
    const int m0 = blockIdx.y * BM;
    const int n0 = blockIdx.x * BN;
    const int ty = tid >> 4, tx = tid & 15;

    if (MODE == 1) {
        if (tid < BM) {
            int r = m0 + tid;
            sIA[tid] = (r < M) ? b2a[r]    : 0;
            sIB[tid] = (r < M) ? b2revb[r] : 0;
        }
        __syncthreads();
    }

    // per-thread load slots
    const int lam = tid >> 4;          // A: base row within tile (+16*i)... actually e-based below
    (void)lam;

    float acc[8][8];
#pragma unroll
    for (int i = 0; i < 8; i++)
#pragma unroll
        for (int j = 0; j < 8; j++) acc[i][j] = 0.f;

    const int nT = (K + BK - 1) / BK;

    // ---- tile load helpers (direct to smem for t=0, regs for pipelined) ----
    float  aReg[8];
    float4 bReg[2];

    auto loadRegs = [&](int k0) {
#pragma unroll
        for (int i = 0; i < 8; i++) {
            int e = tid + i * 256;          // 2048 = 128 x 16
            int m = e >> 4, kq = e & 15;
            int r = m0 + m, kk = k0 + kq;
            float v = 0.f;
            if (r < M && kk < K) {
                if (MODE == 0)
                    v = A[(size_t)r * BF + kk];
                else if (MODE == 1)
                    v = amsg[(size_t)sIA[m] * HD + kk] - msgsrc[(size_t)sIB[m] * HD + kk];
                else
                    v = (kk < AF) ? A[(size_t)r * AF + kk]
                                  : amsg[(size_t)r * HD + (kk - AF)];
            }
            aReg[i] = v;
        }
#pragma unroll
        for (int i = 0; i < 2; i++) {
            int e = tid + i * 256;          // 512 float4 slots = 16 x 32
            int kq = e >> 5, n4 = e & 31;
            int kk = k0 + kq, nn = n0 + n4 * 4;
            float4 v = {0.f, 0.f, 0.f, 0.f};
            if (kk < K && nn < HD) v = *(const float4*)(Bw + (size_t)kk * HD + nn);
            bReg[i] = v;
        }
    };
    auto storeRegs = [&](int s) {
#pragma unroll
        for (int i = 0; i < 8; i++) {
            int e = tid + i * 256;
            int m = e >> 4, kq = e & 15;
            As[s][kq][m] = aReg[i];
        }
#pragma unroll
        for (int i = 0; i < 2; i++) {
            int e = tid + i * 256;
            int kq = e >> 5, n4 = e & 31;
            *(float4*)&Bs[s][kq][n4 * 4] = bReg[i];
        }
    };

    loadRegs(0);
    storeRegs(0);
    __syncthreads();

    for (int t = 0; t < nT; t++) {
        const int cur = t & 1;
        if (t + 1 < nT) loadRegs((t + 1) * BK);

#pragma unroll
        for (int kq = 0; kq < BK; kq++) {
            float4 a0 = *(const float4*)&As[cur][kq][ty * 4];
            float4 a1 = *(const float4*)&As[cur][kq][64 + ty * 4];
            float4 b0 = *(const float4*)&Bs[cur][kq][tx * 4];
            float4 b1 = *(const float4*)&Bs[cur][kq][64 + tx * 4];
            float av[8] = {a0.x, a0.y, a0.z, a0.w, a1.x, a1.y, a1.z, a1.w};
            float bv[8] = {b0.x, b0.y, b0.z, b0.w, b1.x, b1.y, b1.z, b1.w};
#pragma unroll
            for (int i = 0; i < 8; i++)
#pragma unroll
                for (int j = 0; j < 8; j++) acc[i][j] += av[i] * bv[j];
        }
        if (t + 1 < nT) storeRegs((t + 1) & 1);
        __syncthreads();
    }

    // ---- epilogue: rows {ty*4+i, 64+ty*4+i}, cols {tx*4+j, 64+tx*4+j} ------
#pragma unroll
    for (int ih = 0; ih < 2; ih++) {
#pragma unroll
        for (int i = 0; i < 4; i++) {
            int r = m0 + ih * 64 + ty * 4 + i;
            if (r >= M) continue;
#pragma unroll
            for (int jh = 0; jh < 2; jh++) {
                int n = n0 + jh * 64 + tx * 4;
                if (n >= HD) continue;
                size_t o = (size_t)r * HD + n;
                float4 v;
                v.x = acc[ih * 4 + i][jh * 4 + 0];
                v.y = acc[ih * 4 + i][jh * 4 + 1];
                v.z = acc[ih * 4 + i][jh * 4 + 2];
                v.w = acc[ih * 4 + i][jh * 4 + 3];
                if (MODE == 0) {
                    *(float4*)(out2 + o) = v;
                    v.x = fmaxf(v.x, 0.f); v.y = fmaxf(v.y, 0.f);
                    v.z = fmaxf(v.z, 0.f); v.w = fmaxf(v.w, 0.f);
                    *(float4*)(out + o) = v;
                } else if (MODE == 1) {
                    float4 p = *(const float4*)(inp + o);
                    v.x = fmaxf(p.x + v.x, 0.f); v.y = fmaxf(p.y + v.y, 0.f);
                    v.z = fmaxf(p.z + v.z, 0.f); v.w = fmaxf(p.w + v.w, 0.f);
                    *(float4*)(out + o) = v;
                } else {
                    v.x = fmaxf(v.x + bias[n + 0], 0.f);
                    v.y = fmaxf(v.y + bias[n + 1], 0.f);
                    v.z = fmaxf(v.z + bias[n + 2], 0.f);
                    v.w = fmaxf(v.w + bias[n + 3], 0.f);
                    *(float4*)(out + o) = v;
                }
            }
        }
    }
}

// ---------------- neighbor aggregation: amsg[i] = sum_j msg[a2b[i,j]] -------
__global__ void agg_kernel(const float* __restrict__ msg,
                           const int* __restrict__ a2b,
                           float* __restrict__ amsg)
{
    int idx = blockIdx.x * blockDim.x + threadIdx.x;
    if (idx >= NATM * 75) return;
    int i = idx / 75, k4 = idx % 75;
    float4 s = {0.f, 0.f, 0.f, 0.f};
#pragma unroll
    for (int j = 0; j < MAXNB; j++) {
        int b = __ldg(a2b + i * MAXNB + j);
        float4 v = *(const float4*)(msg + (size_t)b * HD + k4 * 4);
        s.x += v.x; s.y += v.y; s.z += v.z; s.w += v.w;
    }
    *(float4*)(amsg + (size_t)i * HD + k4 * 4) = s;
}

// ---------------- undirected pairing ---------------------------------------
__global__ void und_kernel(const float* __restrict__ msg, float* __restrict__ und)
{
    int idx = blockIdx.x * blockDim.x + threadIdx.x;
    if (idx >= NUND * 75) return;
    int r = idx / 75, k4 = idx % 75;
    int r1 = 2 * r;
    int r2 = (r == 0) ? 0 : (2 * r - 1);
    float4 a = *(const float4*)(msg + (size_t)r1 * HD + k4 * 4);
    float4 b = *(const float4*)(msg + (size_t)r2 * HD + k4 * 4);
    float4 o;
    o.x = 0.5f * (a.x + b.x); o.y = 0.5f * (a.y + b.y);
    o.z = 0.5f * (a.z + b.z); o.w = 0.5f * (a.w + b.w);
    *(float4*)(und + (size_t)r * HD + k4 * 4) = o;
}

// ---------------- batchnorm (two-pass, fp64 accumulation) -------------------
__global__ void zero_stats()
{
    int t = threadIdx.x;
    if (t < 2 * HD) {
        (&g_sum[0][0])[t]   = 0.0;
        (&g_sumsq[0][0])[t] = 0.0;
    }
}

__global__ void stats_kernel(const float* __restrict__ x, int rows,
                             double* __restrict__ sum, double* __restrict__ sumsq)
{
    int c = threadIdx.x;
    if (c >= HD) return;
    long r0 = (long)blockIdx.x * 512;
    long r1 = r0 + 512; if (r1 > rows) r1 = rows;
    double s = 0.0, s2 = 0.0;
    for (long r = r0; r < r1; r++) {
        double v = (double)x[(size_t)r * HD + c];
        s += v; s2 += v * v;
    }
    atomicAdd(&sum[c], s);
    atomicAdd(&sumsq[c], s2);
}

// precompute per-column scale/shift so normalization is pure fp32 streaming
__global__ void finalize_stats(int rowsA, int rowsB,
                               const float* __restrict__ gamma,
                               const float* __restrict__ beta)
{
    int t = blockIdx.x * blockDim.x + threadIdx.x;
    if (t >= 2 * HD) return;
    int g = t / HD, c = t % HD;
    long rows = g ? rowsB : rowsA;
    double mu  = g_sum[g][c] / rows;
    double var = g_sumsq[g][c] / rows - mu * mu;
    double sc  = (double)gamma[c] / sqrt(var + 1e-5);
    g_scale[g][c] = (float)sc;
    g_shift[g][c] = beta[c] - (float)(mu * sc);
}

__global__ void norm_kernel(const float* __restrict__ x, long rows, int grp,
                            float* __restrict__ out)
{
    long idx = (long)blockIdx.x * blockDim.x + threadIdx.x;
    long tot = rows * 75;
    if (idx >= tot) return;
    int c4 = (int)(idx % 75);
    float4 v  = *(const float4*)(x + idx * 4 - (idx / 75) * 0);  // x is contiguous: idx*4
    v = *(const float4*)(x + idx * 4);
    float4 sc = *(const float4*)(&g_scale[grp][c4 * 4]);
    float4 sh = *(const float4*)(&g_shift[grp][c4 * 4]);
    float4 o;
    o.x = v.x * sc.x + sh.x; o.y = v.y * sc.y + sh.y;
    o.z = v.z * sc.z + sh.z; o.w = v.w * sc.w + sh.w;
    *(float4*)(out + idx * 4) = o;
}

// ---------------- launch -----------------------------------------------------
extern "C" void kernel_launch(void* const* d_in, const int* in_sizes, int n_in,
                              void* d_out, int out_size)
{
    const float* f_atoms = (const float*)d_in[0];
    const float* f_bonds = (const float*)d_in[1];
    const int*   a2b     = (const int*)  d_in[2];
    const int*   b2a     = (const int*)  d_in[3];
    const int*   b2revb  = (const int*)  d_in[4];
    const float* W_i     = (const float*)d_in[5];
    const float* W_h     = (const float*)d_in[6];
    const float* W_o     = (const float*)d_in[7];
    const float* b_o     = (const float*)d_in[8];
    const float* gamma   = (const float*)d_in[9];
    const float* beta    = (const float*)d_in[10];

    float *inp, *msgA, *msgB, *amsg, *hid, *und;
    double *sum, *sumsq;
    cudaGetSymbolAddress((void**)&inp,  g_inp);
    cudaGetSymbolAddress((void**)&msgA, g_msgA);
    cudaGetSymbolAddress((void**)&msgB, g_msgB);
    cudaGetSymbolAddress((void**)&amsg, g_amsg);
    cudaGetSymbolAddress((void**)&hid,  g_hid);
    cudaGetSymbolAddress((void**)&und,  g_und);
    cudaGetSymbolAddress((void**)&sum,  g_sum);
    cudaGetSymbolAddress((void**)&sumsq,g_sumsq);

    zero_stats<<<1, 1024>>>();

    dim3 gB((HD + BN - 1) / BN, (NBND + BM - 1) / BM);   // 3 x 3126
    dim3 gO((HD + BN - 1) / BN, (NATM + BM - 1) / BM);   // 3 x 782
    const int AGG_G = (NATM * 75 + 255) / 256;

    // inp = f_bonds @ W_i ; msgA = relu(inp)
    gemm_kernel<0><<<gB, 256>>>(f_bonds, W_i, nullptr, nullptr, nullptr,
                                nullptr, nullptr, nullptr, msgA, inp, NBND, BF);
    // depth iteration 1
    agg_kernel<<<AGG_G, 256>>>(msgA, a2b, amsg);
    gemm_kernel<1><<<gB, 256>>>(nullptr, W_h, inp, amsg, msgA,
                                b2a, b2revb, nullptr, msgB, nullptr, NBND, HD);
    // depth iteration 2
    agg_kernel<<<AGG_G, 256>>>(msgB, a2b, amsg);
    gemm_kernel<1><<<gB, 256>>>(nullptr, W_h, inp, amsg, msgB,
                                b2a, b2revb, nullptr, msgA, nullptr, NBND, HD);
    // undirected pairing from final message
    und_kernel<<<(NUND * 75 + 255) / 256, 256>>>(msgA, und);
    // final aggregation + output transform
    agg_kernel<<<AGG_G, 256>>>(msgA, a2b, amsg);
    gemm_kernel<2><<<gO, 256>>>(f_atoms, W_o, nullptr, amsg, nullptr,
                                nullptr, nullptr, b_o, hid, nullptr, NATM, AF + HD);

    // batchnorm over rows [1:]
    stats_kernel<<<(NATM - 1 + 511) / 512, 320>>>(hid + HD, NATM - 1, sum, sumsq);
    stats_kernel<<<(NUND - 1 + 511) / 512, 320>>>(und + HD, NUND - 1, sum + HD, sumsq + HD);
    finalize_stats<<<(2 * HD + 255) / 256, 256>>>(NATM - 1, NUND - 1, gamma, beta);

    float* outp = (float*)d_out;
    long nAtom4 = (long)(NATM - 1) * 75;
    long nBond4 = (long)(NUND - 1) * 75;
    norm_kernel<<<(int)((nAtom4 + 255) / 256), 256>>>(hid + HD, NATM - 1, 0, outp);
    norm_kernel<<<(int)((nBond4 + 255) / 256), 256>>>(und + HD, NUND - 1, 1, outp + nAtom4 * 4);
}

// round 6
// speedup vs baseline: 3.2139x; 1.8424x over previous
#include <cuda_runtime.h>
#include <cuda_bf16.h>
#include <cstdint>
#include <cstddef>

#define NBND 400001
#define NATM 100000
#define HD   300
#define AF   133
#define BF   147
#define MAXNB 6
#define NUND 200001

// ---------------- scratch ---------------------------------------------------
__device__ float g_inp [(size_t)NBND * HD];
__device__ float g_msgA[(size_t)NBND * HD];
__device__ float g_msgB[(size_t)NBND * HD];
__device__ float g_amsg[(size_t)NATM * HD];
__device__ float g_hid [(size_t)NATM * HD];
__device__ float g_und [(size_t)NUND * HD];
__device__ double g_sum  [2][HD];
__device__ double g_sumsq[2][HD];
__device__ float g_scale[2][HD];
__device__ float g_shift[2][HD];

// pre-split, pre-transposed weights: g_B[n][kpad] = W[k][n], bf16 hi/lo, zero pad
__device__ __nv_bfloat16 g_Bi_hi[320 * 160], g_Bi_lo[320 * 160];   // W_i K=147 ->160
__device__ __nv_bfloat16 g_Bh_hi[320 * 320], g_Bh_lo[320 * 320];   // W_h K=300 ->320
__device__ __nv_bfloat16 g_Bo_hi[320 * 448], g_Bo_lo[320 * 448];   // W_o K=433 ->448

// ---------------- mma.sync helper (sm_80+ baseline PTX; no tcgen05) ----------
__device__ __forceinline__ void mma16816(float* c, const uint32_t* a,
                                         uint32_t b0, uint32_t b1) {
    asm volatile(
        "mma.sync.aligned.m16n8k16.row.col.f32.bf16.bf16.f32 "
        "{%0,%1,%2,%3}, {%4,%5,%6,%7}, {%8,%9}, {%0,%1,%2,%3};"
        : "+f"(c[0]), "+f"(c[1]), "+f"(c[2]), "+f"(c[3])
        : "r"(a[0]), "r"(a[1]), "r"(a[2]), "r"(a[3]), "r"(b0), "r"(b1));
}

__device__ __forceinline__ uint32_t pack_hi(float x, float y) {
    __nv_bfloat16 hx = __float2bfloat16(x), hy = __float2bfloat16(y);
    return (uint32_t)__bfloat16_as_ushort(hx) | ((uint32_t)__bfloat16_as_ushort(hy) << 16);
}
__device__ __forceinline__ uint32_t pack_lo(float x, float y) {
    __nv_bfloat16 hx = __float2bfloat16(x), hy = __float2bfloat16(y);
    __nv_bfloat16 lx = __float2bfloat16(x - __bfloat162float(hx));
    __nv_bfloat16 ly = __float2bfloat16(y - __bfloat162float(hy));
    return (uint32_t)__bfloat16_as_ushort(lx) | ((uint32_t)__bfloat16_as_ushort(ly) << 16);
}

// ---------------- HMMA GEMM --------------------------------------------------
// C[M,300] = A[M,K] @ W[K,300]; CTA tile 128x160, warp tile 32x80, BK=32.
// 3-term bf16 split: AhBh + AhBl + AlBh.
// MODE 0: A = f_bonds (K=147). out2 = acc, out = relu(acc)
// MODE 1: A = amsg[b2a[r]] - msgsrc[b2revb[r]] (K=300). out = relu(inp + acc)
// MODE 2: A = concat(f_atoms, amsg) (K=433). out = relu(acc + bias)
constexpr int RSA = 80;                 // smem row stride bytes (40 bf16)
constexpr int OFF_AH = 0;               // 128*80 = 10240
constexpr int OFF_AL = 10240;
constexpr int OFF_BH = 20480;           // 160*80 = 12800
constexpr int OFF_BL = 33280;
constexpr int STAGE  = 46080;
constexpr int SMEM_TOTAL = 2 * STAGE;   // 92160

template <int MODE>
__global__ __launch_bounds__(256, 1) void tc_gemm(
    const float* __restrict__ A,
    const __nv_bfloat16* __restrict__ Bhi,
    const __nv_bfloat16* __restrict__ Blo,
    const float* __restrict__ inp,
    const float* __restrict__ amsg,
    const float* __restrict__ msgsrc,
    const int*   __restrict__ b2a,
    const int*   __restrict__ b2revb,
    const float* __restrict__ bias,
    float* __restrict__ out,
    float* __restrict__ out2,
    int M)
{
    constexpr int K    = (MODE == 0) ? BF : (MODE == 1) ? HD : (AF + HD);
    constexpr int NC   = (K + 31) / 32;
    constexpr int KPAD = NC * 32;

    extern __shared__ char smem[];
    const int tid = threadIdx.x;
    const int wid = tid >> 5, lid = tid & 31;
    const int wm = wid & 3, wn = wid >> 2;
    const int grp = lid >> 2, thr = lid & 3;
    const int m0 = blockIdx.y * 128;
    const int n0 = blockIdx.x * 160;

    // MODE1 gather pointers (hoisted)
    const float4* pa = nullptr; const float4* pb = nullptr;
    int rowvalid = 0;
    const int arow_ld = tid >> 1;             // row this thread loads
    const int kh_ld   = (tid & 1) * 16;       // k-half within chunk
    if (MODE == 1) {
        int gr = m0 + arow_ld;
        rowvalid = (gr < M);
        int ia = rowvalid ? b2a[gr] : 0;
        int ib = rowvalid ? b2revb[gr] : 0;
        pa = (const float4*)(amsg   + (size_t)ia * HD);
        pb = (const float4*)(msgsrc + (size_t)ib * HD);
    }

    float acc[2][10][4];
#pragma unroll
    for (int mf = 0; mf < 2; mf++)
#pragma unroll
        for (int nf = 0; nf < 10; nf++)
#pragma unroll
            for (int q = 0; q < 4; q++) acc[mf][nf][q] = 0.f;

    float fa[16];            // A prefetch (floats; split at store)
    uint2 bhR[5], blR[5];    // B prefetch

    auto loadRegs = [&](int c) {
        const int k0 = c * 32;
        if (MODE == 1) {
#pragma unroll
            for (int j = 0; j < 4; j++) {
                int k = k0 + kh_ld + j * 4;
                float4 v = {0.f, 0.f, 0.f, 0.f};
                if (rowvalid && k < HD) {
                    float4 x = pa[k >> 2], y = pb[k >> 2];
                    v.x = x.x - y.x; v.y = x.y - y.y; v.z = x.z - y.z; v.w = x.w - y.w;
                }
                fa[j * 4 + 0] = v.x; fa[j * 4 + 1] = v.y;
                fa[j * 4 + 2] = v.z; fa[j * 4 + 3] = v.w;
            }
        } else {
#pragma unroll
            for (int i = 0; i < 16; i++) {
                int idx = tid + i * 256;      // 128*32 = 4096
                int r = idx >> 5, kl = idx & 31;
                int gr = m0 + r, k = k0 + kl;
                float v = 0.f;
                if (gr < M) {
                    if (MODE == 0) { if (k < BF) v = A[(size_t)gr * BF + k]; }
                    else {
                        if (k < AF) v = A[(size_t)gr * AF + k];
                        else if (k < AF + HD) v = amsg[(size_t)gr * HD + (k - AF)];
                    }
                }
                fa[i] = v;
            }
        }
#pragma unroll
        for (int i = 0; i < 5; i++) {
            int idx = tid + i * 256;          // 160*8 = 1280 quads of 4 bf16
            int n = idx >> 3, g = idx & 7;
            size_t src = (size_t)(n0 + n) * KPAD + k0 + g * 4;   // FIX: n0 + n
            bhR[i] = *(const uint2*)(Bhi + src);
            blR[i] = *(const uint2*)(Blo + src);
        }
    };
    auto storeRegs = [&](int buf) {
        char* st = smem + buf * STAGE;
        if (MODE == 1) {
            char* dh = st + OFF_AH + arow_ld * RSA + kh_ld * 2;
            char* dl = st + OFF_AL + arow_ld * RSA + kh_ld * 2;
#pragma unroll
            for (int j = 0; j < 8; j++) {
                float x = fa[j * 2], y = fa[j * 2 + 1];
                *(uint32_t*)(dh + j * 4) = pack_hi(x, y);
                *(uint32_t*)(dl + j * 4) = pack_lo(x, y);
            }
        } else {
#pragma unroll
            for (int i = 0; i < 16; i++) {
                int idx = tid + i * 256;
                int r = idx >> 5, kl = idx & 31;
                float v = fa[i];
                __nv_bfloat16 h = __float2bfloat16(v);
                __nv_bfloat16 l = __float2bfloat16(v - __bfloat162float(h));
                *(__nv_bfloat16*)(st + OFF_AH + r * RSA + kl * 2) = h;
                *(__nv_bfloat16*)(st + OFF_AL + r * RSA + kl * 2) = l;
            }
        }
#pragma unroll
        for (int i = 0; i < 5; i++) {
            int idx = tid + i * 256;
            int n = idx >> 3, g = idx & 7;
            *(uint2*)(st + OFF_BH + n * RSA + g * 8) = bhR[i];
            *(uint2*)(st + OFF_BL + n * RSA + g * 8) = blR[i];
        }
    };

    loadRegs(0);
    storeRegs(0);
    __syncthreads();

    for (int c = 0; c < NC; c++) {
        if (c + 1 < NC) loadRegs(c + 1);

        const char* st = smem + (c & 1) * STAGE;
#pragma unroll
        for (int s = 0; s < 2; s++) {
            const int kb = s * 32 + thr * 4;     // byte offset of this thread's k16 pair
            // A fragments
            uint32_t ah[2][4], al[2][4];
#pragma unroll
            for (int mf = 0; mf < 2; mf++) {
                int base = (wm * 32 + mf * 16 + grp) * RSA + kb;
                ah[mf][0] = *(const uint32_t*)(st + OFF_AH + base);
                ah[mf][1] = *(const uint32_t*)(st + OFF_AH + base + 8 * RSA);
                ah[mf][2] = *(const uint32_t*)(st + OFF_AH + base + 16);
                ah[mf][3] = *(const uint32_t*)(st + OFF_AH + base + 8 * RSA + 16);
                al[mf][0] = *(const uint32_t*)(st + OFF_AL + base);
                al[mf][1] = *(const uint32_t*)(st + OFF_AL + base + 8 * RSA);
                al[mf][2] = *(const uint32_t*)(st + OFF_AL + base + 16);
                al[mf][3] = *(const uint32_t*)(st + OFF_AL + base + 8 * RSA + 16);
            }
#pragma unroll
            for (int nf = 0; nf < 10; nf++) {
                int bb = (wn * 80 + nf * 8 + grp) * RSA + kb;
                uint32_t bh0 = *(const uint32_t*)(st + OFF_BH + bb);
                uint32_t bh1 = *(const uint32_t*)(st + OFF_BH + bb + 16);
                uint32_t bl0 = *(const uint32_t*)(st + OFF_BL + bb);
                uint32_t bl1 = *(const uint32_t*)(st + OFF_BL + bb + 16);
#pragma unroll
                for (int mf = 0; mf < 2; mf++) {
                    mma16816(acc[mf][nf], ah[mf], bh0, bh1);
                    mma16816(acc[mf][nf], ah[mf], bl0, bl1);
                    mma16816(acc[mf][nf], al[mf], bh0, bh1);
                }
            }
        }
        if (c + 1 < NC) storeRegs((c + 1) & 1);
        __syncthreads();
    }

    // ---- epilogue: fragment layout c0,c1=(row,col..col+1) c2,c3=(row+8) ----
#pragma unroll
    for (int mf = 0; mf < 2; mf++) {
#pragma unroll
        for (int nf = 0; nf < 10; nf++) {
            int col = n0 + wn * 80 + nf * 8 + thr * 2;
            if (col >= HD) continue;
            int row0 = m0 + wm * 32 + mf * 16 + grp;
#pragma unroll
            for (int h = 0; h < 2; h++) {
                int r = row0 + h * 8;
                if (r >= M) continue;
                size_t o = (size_t)r * HD + col;
                float vx = acc[mf][nf][h * 2 + 0];
                float vy = acc[mf][nf][h * 2 + 1];
                if (MODE == 0) {
                    *(float2*)(out2 + o) = make_float2(vx, vy);
                    *(float2*)(out  + o) = make_float2(fmaxf(vx, 0.f), fmaxf(vy, 0.f));
                } else if (MODE == 1) {
                    float2 p = *(const float2*)(inp + o);
                    *(float2*)(out + o) = make_float2(fmaxf(p.x + vx, 0.f),
                                                      fmaxf(p.y + vy, 0.f));
                } else {
                    *(float2*)(out + o) = make_float2(fmaxf(vx + bias[col], 0.f),
                                                      fmaxf(vy + bias[col + 1], 0.f));
                }
            }
        }
    }
}

// ---------------- weight split/transpose prep --------------------------------
__global__ void split_w(const float* __restrict__ W, int K, int kpad,
                        __nv_bfloat16* __restrict__ hi, __nv_bfloat16* __restrict__ lo)
{
    int idx = blockIdx.x * blockDim.x + threadIdx.x;
    if (idx >= 320 * kpad) return;
    int n = idx / kpad, k = idx % kpad;
    float v = (n < HD && k < K) ? W[(size_t)k * HD + n] : 0.f;
    __nv_bfloat16 h = __float2bfloat16(v);
    hi[idx] = h;
    lo[idx] = __float2bfloat16(v - __bfloat162float(h));
}

// ---------------- aggregation / pairing / batchnorm --------------------------
__global__ void agg_kernel(const float* __restrict__ msg,
                           const int* __restrict__ a2b,
                           float* __restrict__ amsg)
{
    int idx = blockIdx.x * blockDim.x + threadIdx.x;
    if (idx >= NATM * 75) return;
    int i = idx / 75, k4 = idx % 75;
    float4 s = {0.f, 0.f, 0.f, 0.f};
#pragma unroll
    for (int j = 0; j < MAXNB; j++) {
        int b = __ldg(a2b + i * MAXNB + j);
        float4 v = *(const float4*)(msg + (size_t)b * HD + k4 * 4);
        s.x += v.x; s.y += v.y; s.z += v.z; s.w += v.w;
    }
    *(float4*)(amsg + (size_t)i * HD + k4 * 4) = s;
}

__global__ void und_kernel(const float* __restrict__ msg, float* __restrict__ und)
{
    int idx = blockIdx.x * blockDim.x + threadIdx.x;
    if (idx >= NUND * 75) return;
    int r = idx / 75, k4 = idx % 75;
    int r1 = 2 * r;
    int r2 = (r == 0) ? 0 : (2 * r - 1);
    float4 a = *(const float4*)(msg + (size_t)r1 * HD + k4 * 4);
    float4 b = *(const float4*)(msg + (size_t)r2 * HD + k4 * 4);
    float4 o;
    o.x = 0.5f * (a.x + b.x); o.y = 0.5f * (a.y + b.y);
    o.z = 0.5f * (a.z + b.z); o.w = 0.5f * (a.w + b.w);
    *(float4*)(und + (size_t)r * HD + k4 * 4) = o;
}

__global__ void zero_stats()
{
    int t = threadIdx.x;
    if (t < 2 * HD) {
        (&g_sum[0][0])[t]   = 0.0;
        (&g_sumsq[0][0])[t] = 0.0;
    }
}

__global__ void stats_kernel(const float* __restrict__ x, int rows,
                             double* __restrict__ sum, double* __restrict__ sumsq)
{
    int c = threadIdx.x;
    if (c >= HD) return;
    long r0 = (long)blockIdx.x * 512;
    long r1 = r0 + 512; if (r1 > rows) r1 = rows;
    double s = 0.0, s2 = 0.0;
    for (long r = r0; r < r1; r++) {
        double v = (double)x[(size_t)r * HD + c];
        s += v; s2 += v * v;
    }
    atomicAdd(&sum[c], s);
    atomicAdd(&sumsq[c], s2);
}

__global__ void finalize_stats(int rowsA, int rowsB,
                               const float* __restrict__ gamma,
                               const float* __restrict__ beta)
{
    int t = blockIdx.x * blockDim.x + threadIdx.x;
    if (t >= 2 * HD) return;
    int g = t / HD, c = t % HD;
    long rows = g ? rowsB : rowsA;
    double mu  = g_sum[g][c] / rows;
    double var = g_sumsq[g][c] / rows - mu * mu;
    double sc  = (double)gamma[c] / sqrt(var + 1e-5);
    g_scale[g][c] = (float)sc;
    g_shift[g][c] = beta[c] - (float)(mu * sc);
}

__global__ void norm_kernel(const float* __restrict__ x, long rows, int grp,
                            float* __restrict__ out)
{
    long idx = (long)blockIdx.x * blockDim.x + threadIdx.x;
    if (idx >= rows * 75) return;
    int c4 = (int)(idx % 75);
    float4 v  = *(const float4*)(x + idx * 4);
    float4 sc = *(const float4*)(&g_scale[grp][c4 * 4]);
    float4 sh = *(const float4*)(&g_shift[grp][c4 * 4]);
    float4 o;
    o.x = v.x * sc.x + sh.x; o.y = v.y * sc.y + sh.y;
    o.z = v.z * sc.z + sh.z; o.w = v.w * sc.w + sh.w;
    *(float4*)(out + idx * 4) = o;
}

// ---------------- launch ------------------------------------------------------
extern "C" void kernel_launch(void* const* d_in, const int* in_sizes, int n_in,
                              void* d_out, int out_size)
{
    const float* f_atoms = (const float*)d_in[0];
    const float* f_bonds = (const float*)d_in[1];
    const int*   a2b     = (const int*)  d_in[2];
    const int*   b2a     = (const int*)  d_in[3];
    const int*   b2revb  = (const int*)  d_in[4];
    const float* W_i     = (const float*)d_in[5];
    const float* W_h     = (const float*)d_in[6];
    const float* W_o     = (const float*)d_in[7];
    const float* b_o     = (const float*)d_in[8];
    const float* gamma   = (const float*)d_in[9];
    const float* beta    = (const float*)d_in[10];

    float *inp, *msgA, *msgB, *amsg, *hid, *und;
    double *sum, *sumsq;
    __nv_bfloat16 *bi_h, *bi_l, *bh_h, *bh_l, *bo_h, *bo_l;
    cudaGetSymbolAddress((void**)&inp,  g_inp);
    cudaGetSymbolAddress((void**)&msgA, g_msgA);
    cudaGetSymbolAddress((void**)&msgB, g_msgB);
    cudaGetSymbolAddress((void**)&amsg, g_amsg);
    cudaGetSymbolAddress((void**)&hid,  g_hid);
    cudaGetSymbolAddress((void**)&und,  g_und);
    cudaGetSymbolAddress((void**)&sum,  g_sum);
    cudaGetSymbolAddress((void**)&sumsq,g_sumsq);
    cudaGetSymbolAddress((void**)&bi_h, g_Bi_hi);
    cudaGetSymbolAddress((void**)&bi_l, g_Bi_lo);
    cudaGetSymbolAddress((void**)&bh_h, g_Bh_hi);
    cudaGetSymbolAddress((void**)&bh_l, g_Bh_lo);
    cudaGetSymbolAddress((void**)&bo_h, g_Bo_hi);
    cudaGetSymbolAddress((void**)&bo_l, g_Bo_lo);

    cudaFuncSetAttribute(tc_gemm<0>, cudaFuncAttributeMaxDynamicSharedMemorySize, SMEM_TOTAL);
    cudaFuncSetAttribute(tc_gemm<1>, cudaFuncAttributeMaxDynamicSharedMemorySize, SMEM_TOTAL);
    cudaFuncSetAttribute(tc_gemm<2>, cudaFuncAttributeMaxDynamicSharedMemorySize, SMEM_TOTAL);

    zero_stats<<<1, 1024>>>();
    split_w<<<(320 * 160 + 255) / 256, 256>>>(W_i, BF, 160, bi_h, bi_l);
    split_w<<<(320 * 320 + 255) / 256, 256>>>(W_h, HD, 320, bh_h, bh_l);
    split_w<<<(320 * 448 + 255) / 256, 256>>>(W_o, AF + HD, 448, bo_h, bo_l);

    dim3 gB(2, (NBND + 127) / 128);   // 2 x 3126
    dim3 gO(2, (NATM + 127) / 128);   // 2 x 782
    const int AGG_G = (NATM * 75 + 255) / 256;

    tc_gemm<0><<<gB, 256, SMEM_TOTAL>>>(f_bonds, bi_h, bi_l, nullptr, nullptr, nullptr,
                                        nullptr, nullptr, nullptr, msgA, inp, NBND);
    agg_kernel<<<AGG_G, 256>>>(msgA, a2b, amsg);
    tc_gemm<1><<<gB, 256, SMEM_TOTAL>>>(nullptr, bh_h, bh_l, inp, amsg, msgA,
                                        b2a, b2revb, nullptr, msgB, nullptr, NBND);
    agg_kernel<<<AGG_G, 256>>>(msgB, a2b, amsg);
    tc_gemm<1><<<gB, 256, SMEM_TOTAL>>>(nullptr, bh_h, bh_l, inp, amsg, msgB,
                                        b2a, b2revb, nullptr, msgA, nullptr, NBND);
    und_kernel<<<(NUND * 75 + 255) / 256, 256>>>(msgA, und);
    agg_kernel<<<AGG_G, 256>>>(msgA, a2b, amsg);
    tc_gemm<2><<<gO, 256, SMEM_TOTAL>>>(f_atoms, bo_h, bo_l, nullptr, amsg, nullptr,
                                        nullptr, nullptr, b_o, hid, nullptr, NATM);

    stats_kernel<<<(NATM - 1 + 511) / 512, 320>>>(hid + HD, NATM - 1, sum, sumsq);
    stats_kernel<<<(NUND - 1 + 511) / 512, 320>>>(und + HD, NUND - 1, sum + HD, sumsq + HD);
    finalize_stats<<<(2 * HD + 255) / 256, 256>>>(NATM - 1, NUND - 1, gamma, beta);

    float* outp = (float*)d_out;
    long nAtom4 = (long)(NATM - 1) * 75;
    long nBond4 = (long)(NUND - 1) * 75;
    norm_kernel<<<(int)((nAtom4 + 255) / 256), 256>>>(hid + HD, NATM - 1, 0, outp);
    norm_kernel<<<(int)((nBond4 + 255) / 256), 256>>>(und + HD, NUND - 1, 1, outp + nAtom4 * 4);
}

// round 7
// speedup vs baseline: 3.7878x; 1.1786x over previous
#include <cuda_runtime.h>
#include <cuda_bf16.h>
#include <cstdint>
#include <cstddef>

#define NBND 400001
#define NATM 100000
#define HD   300
#define AF   133
#define BF   147
#define MAXNB 6
#define NUND 200001

// ---------------- scratch ---------------------------------------------------
__device__ float g_inp [(size_t)NBND * HD];
__device__ float g_msgA[(size_t)NBND * HD];
__device__ float g_msgB[(size_t)NBND * HD];
__device__ float g_amsg[(size_t)NATM * HD];
__device__ float g_hid [(size_t)NATM * HD];
__device__ double g_sum  [2][HD];
__device__ double g_sumsq[2][HD];
__device__ float g_scale[2][HD];
__device__ float g_shift[2][HD];

// pre-split, pre-transposed weights: g_B[n][kpad] = W[k][n], bf16 hi/lo, zero pad
__device__ __nv_bfloat16 g_Bi_hi[320 * 160], g_Bi_lo[320 * 160];   // W_i K=147 ->160
__device__ __nv_bfloat16 g_Bh_hi[320 * 320], g_Bh_lo[320 * 320];   // W_h K=300 ->320
__device__ __nv_bfloat16 g_Bo_hi[320 * 448], g_Bo_lo[320 * 448];   // W_o K=433 ->448

// ---------------- mma.sync helper (sm_80+ baseline PTX) ----------------------
__device__ __forceinline__ void mma16816(float* c, const uint32_t* a,
                                         uint32_t b0, uint32_t b1) {
    asm volatile(
        "mma.sync.aligned.m16n8k16.row.col.f32.bf16.bf16.f32 "
        "{%0,%1,%2,%3}, {%4,%5,%6,%7}, {%8,%9}, {%0,%1,%2,%3};"
        : "+f"(c[0]), "+f"(c[1]), "+f"(c[2]), "+f"(c[3])
        : "r"(a[0]), "r"(a[1]), "r"(a[2]), "r"(a[3]), "r"(b0), "r"(b1));
}

__device__ __forceinline__ uint32_t pack_hi(float x, float y) {
    __nv_bfloat16 hx = __float2bfloat16(x), hy = __float2bfloat16(y);
    return (uint32_t)__bfloat16_as_ushort(hx) | ((uint32_t)__bfloat16_as_ushort(hy) << 16);
}
__device__ __forceinline__ uint32_t pack_lo(float x, float y) {
    __nv_bfloat16 hx = __float2bfloat16(x), hy = __float2bfloat16(y);
    __nv_bfloat16 lx = __float2bfloat16(x - __bfloat162float(hx));
    __nv_bfloat16 ly = __float2bfloat16(y - __bfloat162float(hy));
    return (uint32_t)__bfloat16_as_ushort(lx) | ((uint32_t)__bfloat16_as_ushort(ly) << 16);
}

// ---------------- HMMA GEMM --------------------------------------------------
// C[M,300] = A[M,K] @ W[K,300]; CTA tile 64x320 (full width, A gathered once),
// warp tile 32x80 (8 warps = 2m x 4n), BK=32, double-buffered smem.
// 3-term bf16 split: AhBh + AhBl + AlBh.
// MODE 0: A = f_bonds (K=147). out2 = acc, out = relu(acc)
// MODE 1: A = amsg[b2a[r]] - msgsrc[b2revb[r]] (K=300). out = relu(inp + acc)
// MODE 2: A = concat(f_atoms, amsg) (K=433). out = relu(acc + bias)
constexpr int RSA = 80;                 // smem row stride bytes (40 bf16)
constexpr int OFF_AH = 0;               // 64*80  = 5120
constexpr int OFF_AL = 5120;
constexpr int OFF_BH = 10240;           // 320*80 = 25600
constexpr int OFF_BL = 35840;
constexpr int STAGE  = 61440;
constexpr int SMEM_TOTAL = 2 * STAGE;   // 122880

template <int MODE>
__global__ __launch_bounds__(256, 1) void tc_gemm(
    const float* __restrict__ A,
    const __nv_bfloat16* __restrict__ Bhi,
    const __nv_bfloat16* __restrict__ Blo,
    const float* __restrict__ inp,
    const float* __restrict__ amsg,
    const float* __restrict__ msgsrc,
    const int*   __restrict__ b2a,
    const int*   __restrict__ b2revb,
    const float* __restrict__ bias,
    float* __restrict__ out,
    float* __restrict__ out2,
    int M)
{
    constexpr int K    = (MODE == 0) ? BF : (MODE == 1) ? HD : (AF + HD);
    constexpr int NC   = (K + 31) / 32;
    constexpr int KPAD = NC * 32;

    extern __shared__ char smem[];
    const int tid = threadIdx.x;
    const int wid = tid >> 5, lid = tid & 31;
    const int wm = wid & 1, wn = wid >> 1;          // 2m x 4n warp grid
    const int grp = lid >> 2, thr = lid & 3;
    const int m0 = blockIdx.y * 64;

    // MODE1 gather pointers (one row per 4 threads)
    const float4* pa = nullptr; const float4* pb = nullptr;
    int rowvalid = 0;
    const int arow_ld = tid >> 2;             // row 0..63
    const int kq_ld   = (tid & 3) * 8;        // k offset 0,8,16,24 within chunk
    if (MODE == 1) {
        int gr = m0 + arow_ld;
        rowvalid = (gr < M);
        int ia = rowvalid ? b2a[gr] : 0;
        int ib = rowvalid ? b2revb[gr] : 0;
        pa = (const float4*)(amsg   + (size_t)ia * HD);
        pb = (const float4*)(msgsrc + (size_t)ib * HD);
    }

    float acc[2][10][4];
#pragma unroll
    for (int mf = 0; mf < 2; mf++)
#pragma unroll
        for (int nf = 0; nf < 10; nf++)
#pragma unroll
            for (int q = 0; q < 4; q++) acc[mf][nf][q] = 0.f;

    float fa[8];             // A prefetch
    uint2 bhR[10], blR[10];  // B prefetch (320 rows x 8 quads / 256 thr)

    auto loadRegs = [&](int c) {
        const int k0 = c * 32;
        if (MODE == 1) {
#pragma unroll
            for (int j = 0; j < 2; j++) {
                int k = k0 + kq_ld + j * 4;
                float4 v = {0.f, 0.f, 0.f, 0.f};
                if (rowvalid && k + 3 < HD) {
                    float4 x = pa[k >> 2], y = pb[k >> 2];
                    v.x = x.x - y.x; v.y = x.y - y.y; v.z = x.z - y.z; v.w = x.w - y.w;
                }
                fa[j * 4 + 0] = v.x; fa[j * 4 + 1] = v.y;
                fa[j * 4 + 2] = v.z; fa[j * 4 + 3] = v.w;
            }
        } else {
#pragma unroll
            for (int i = 0; i < 8; i++) {
                int idx = tid + i * 256;      // 64*32 = 2048
                int r = idx >> 5, kl = idx & 31;
                int gr = m0 + r, k = k0 + kl;
                float v = 0.f;
                if (gr < M) {
                    if (MODE == 0) { if (k < BF) v = A[(size_t)gr * BF + k]; }
                    else {
                        if (k < AF) v = A[(size_t)gr * AF + k];
                        else if (k < AF + HD) v = amsg[(size_t)gr * HD + (k - AF)];
                    }
                }
                fa[i] = v;
            }
        }
#pragma unroll
        for (int i = 0; i < 10; i++) {
            int idx = tid + i * 256;          // 320*8 = 2560 quads of 4 bf16
            int n = idx >> 3, g = idx & 7;
            size_t src = (size_t)n * KPAD + k0 + g * 4;
            bhR[i] = *(const uint2*)(Bhi + src);
            blR[i] = *(const uint2*)(Blo + src);
        }
    };
    auto storeRegs = [&](int buf) {
        char* st = smem + buf * STAGE;
        if (MODE == 1) {
            char* dh = st + OFF_AH + arow_ld * RSA + kq_ld * 2;
            char* dl = st + OFF_AL + arow_ld * RSA + kq_ld * 2;
#pragma unroll
            for (int j = 0; j < 4; j++) {
                float x = fa[j * 2], y = fa[j * 2 + 1];
                *(uint32_t*)(dh + j * 4) = pack_hi(x, y);
                *(uint32_t*)(dl + j * 4) = pack_lo(x, y);
            }
        } else {
#pragma unroll
            for (int i = 0; i < 8; i++) {
                int idx = tid + i * 256;
                int r = idx >> 5, kl = idx & 31;
                float v = fa[i];
                __nv_bfloat16 h = __float2bfloat16(v);
                __nv_bfloat16 l = __float2bfloat16(v - __bfloat162float(h));
                *(__nv_bfloat16*)(st + OFF_AH + r * RSA + kl * 2) = h;
                *(__nv_bfloat16*)(st + OFF_AL + r * RSA + kl * 2) = l;
            }
        }
#pragma unroll
        for (int i = 0; i < 10; i++) {
            int idx = tid + i * 256;
            int n = idx >> 3, g = idx & 7;
            *(uint2*)(st + OFF_BH + n * RSA + g * 8) = bhR[i];
            *(uint2*)(st + OFF_BL + n * RSA + g * 8) = blR[i];
        }
    };

    loadRegs(0);
    storeRegs(0);
    __syncthreads();

    for (int c = 0; c < NC; c++) {
        if (c + 1 < NC) loadRegs(c + 1);

        const char* st = smem + (c & 1) * STAGE;
#pragma unroll
        for (int s = 0; s < 2; s++) {
            const int kb = s * 32 + thr * 4;
            uint32_t ah[2][4], al[2][4];
#pragma unroll
            for (int mf = 0; mf < 2; mf++) {
                int base = (wm * 32 + mf * 16 + grp) * RSA + kb;
                ah[mf][0] = *(const uint32_t*)(st + OFF_AH + base);
                ah[mf][1] = *(const uint32_t*)(st + OFF_AH + base + 8 * RSA);
                ah[mf][2] = *(const uint32_t*)(st + OFF_AH + base + 16);
                ah[mf][3] = *(const uint32_t*)(st + OFF_AH + base + 8 * RSA + 16);
                al[mf][0] = *(const uint32_t*)(st + OFF_AL + base);
                al[mf][1] = *(const uint32_t*)(st + OFF_AL + base + 8 * RSA);
                al[mf][2] = *(const uint32_t*)(st + OFF_AL + base + 16);
                al[mf][3] = *(const uint32_t*)(st + OFF_AL + base + 8 * RSA + 16);
            }
#pragma unroll
            for (int nf = 0; nf < 10; nf++) {
                int bb = (wn * 80 + nf * 8 + grp) * RSA + kb;
                uint32_t bh0 = *(const uint32_t*)(st + OFF_BH + bb);
                uint32_t bh1 = *(const uint32_t*)(st + OFF_BH + bb + 16);
                uint32_t bl0 = *(const uint32_t*)(st + OFF_BL + bb);
                uint32_t bl1 = *(const uint32_t*)(st + OFF_BL + bb + 16);
#pragma unroll
                for (int mf = 0; mf < 2; mf++) {
                    mma16816(acc[mf][nf], ah[mf], bh0, bh1);
                    mma16816(acc[mf][nf], ah[mf], bl0, bl1);
                    mma16816(acc[mf][nf], al[mf], bh0, bh1);
                }
            }
        }
        if (c + 1 < NC) storeRegs((c + 1) & 1);
        __syncthreads();
    }

    // ---- epilogue ----
#pragma unroll
    for (int mf = 0; mf < 2; mf++) {
#pragma unroll
        for (int nf = 0; nf < 10; nf++) {
            int col = wn * 80 + nf * 8 + thr * 2;
            if (col >= HD) continue;
            int row0 = m0 + wm * 32 + mf * 16 + grp;
#pragma unroll
            for (int h = 0; h < 2; h++) {
                int r = row0 + h * 8;
                if (r >= M) continue;
                size_t o = (size_t)r * HD + col;
                float vx = acc[mf][nf][h * 2 + 0];
                float vy = acc[mf][nf][h * 2 + 1];
                if (MODE == 0) {
                    *(float2*)(out2 + o) = make_float2(vx, vy);
                    *(float2*)(out  + o) = make_float2(fmaxf(vx, 0.f), fmaxf(vy, 0.f));
                } else if (MODE == 1) {
                    float2 p = *(const float2*)(inp + o);
                    *(float2*)(out + o) = make_float2(fmaxf(p.x + vx, 0.f),
                                                      fmaxf(p.y + vy, 0.f));
                } else {
                    *(float2*)(out + o) = make_float2(fmaxf(vx + bias[col], 0.f),
                                                      fmaxf(vy + bias[col + 1], 0.f));
                }
            }
        }
    }
}

// ---------------- weight split/transpose prep --------------------------------
__global__ void split_w(const float* __restrict__ W, int K, int kpad,
                        __nv_bfloat16* __restrict__ hi, __nv_bfloat16* __restrict__ lo)
{
    int idx = blockIdx.x * blockDim.x + threadIdx.x;
    if (idx >= 320 * kpad) return;
    int n = idx / kpad, k = idx % kpad;
    float v = (n < HD && k < K) ? W[(size_t)k * HD + n] : 0.f;
    __nv_bfloat16 h = __float2bfloat16(v);
    hi[idx] = h;
    lo[idx] = __float2bfloat16(v - __bfloat162float(h));
}

// ---------------- aggregation ------------------------------------------------
__global__ void agg_kernel(const float* __restrict__ msg,
                           const int* __restrict__ a2b,
                           float* __restrict__ amsg)
{
    int idx = blockIdx.x * blockDim.x + threadIdx.x;
    if (idx >= NATM * 75) return;
    int i = idx / 75, k4 = idx % 75;
    float4 s = {0.f, 0.f, 0.f, 0.f};
#pragma unroll
    for (int j = 0; j < MAXNB; j++) {
        int b = __ldg(a2b + i * MAXNB + j);
        float4 v = *(const float4*)(msg + (size_t)b * HD + k4 * 4);
        s.x += v.x; s.y += v.y; s.z += v.z; s.w += v.w;
    }
    *(float4*)(amsg + (size_t)i * HD + k4 * 4) = s;
}

// ---------------- batchnorm (two-pass, fp64 accumulation) --------------------
__global__ void zero_stats()
{
    int t = threadIdx.x;
    if (t < 2 * HD) {
        (&g_sum[0][0])[t]   = 0.0;
        (&g_sumsq[0][0])[t] = 0.0;
    }
}

__global__ void stats_kernel(const float* __restrict__ x, int rows,
                             double* __restrict__ sum, double* __restrict__ sumsq)
{
    int c = threadIdx.x;
    if (c >= HD) return;
    long r0 = (long)blockIdx.x * 512;
    long r1 = r0 + 512; if (r1 > rows) r1 = rows;
    double s = 0.0, s2 = 0.0;
    for (long r = r0; r < r1; r++) {
        double v = (double)x[(size_t)r * HD + c];
        s += v; s2 += v * v;
    }
    atomicAdd(&sum[c], s);
    atomicAdd(&sumsq[c], s2);
}

// fused undirected pairing + stats: rows 1..NUND-1, val = (msg[2r]+msg[2r-1])/2
__global__ void stats_und_kernel(const float* __restrict__ msg,
                                 double* __restrict__ sum, double* __restrict__ sumsq)
{
    int c = threadIdx.x;
    if (c >= HD) return;
    long r0 = (long)blockIdx.x * 512 + 1;
    long r1 = r0 + 512; if (r1 > NUND) r1 = NUND;
    double s = 0.0, s2 = 0.0;
    for (long r = r0; r < r1; r++) {
        float v = 0.5f * (msg[(size_t)(2 * r) * HD + c] + msg[(size_t)(2 * r - 1) * HD + c]);
        double d = (double)v;
        s += d; s2 += d * d;
    }
    atomicAdd(&sum[c], s);
    atomicAdd(&sumsq[c], s2);
}

__global__ void finalize_stats(int rowsA, int rowsB,
                               const float* __restrict__ gamma,
                               const float* __restrict__ beta)
{
    int t = blockIdx.x * blockDim.x + threadIdx.x;
    if (t >= 2 * HD) return;
    int g = t / HD, c = t % HD;
    long rows = g ? rowsB : rowsA;
    double mu  = g_sum[g][c] / rows;
    double var = g_sumsq[g][c] / rows - mu * mu;
    double sc  = (double)gamma[c] / sqrt(var + 1e-5);
    g_scale[g][c] = (float)sc;
    g_shift[g][c] = beta[c] - (float)(mu * sc);
}

__global__ void norm_kernel(const float* __restrict__ x, long rows, int grp,
                            float* __restrict__ out)
{
    long idx = (long)blockIdx.x * blockDim.x + threadIdx.x;
    if (idx >= rows * 75) return;
    int c4 = (int)(idx % 75);
    float4 v  = *(const float4*)(x + idx * 4);
    float4 sc = *(const float4*)(&g_scale[grp][c4 * 4]);
    float4 sh = *(const float4*)(&g_shift[grp][c4 * 4]);
    float4 o;
    o.x = v.x * sc.x + sh.x; o.y = v.y * sc.y + sh.y;
    o.z = v.z * sc.z + sh.z; o.w = v.w * sc.w + sh.w;
    *(float4*)(out + idx * 4) = o;
}

// fused undirected pairing + normalize (bonds output)
__global__ void norm_und_kernel(const float* __restrict__ msg, float* __restrict__ out)
{
    long idx = (long)blockIdx.x * blockDim.x + threadIdx.x;
    if (idx >= (long)(NUND - 1) * 75) return;
    long r = idx / 75 + 1;
    int c4 = (int)(idx % 75);
    float4 a = *(const float4*)(msg + (size_t)(2 * r) * HD + c4 * 4);
    float4 b = *(const float4*)(msg + (size_t)(2 * r - 1) * HD + c4 * 4);
    float4 sc = *(const float4*)(&g_scale[1][c4 * 4]);
    float4 sh = *(const float4*)(&g_shift[1][c4 * 4]);
    float4 o;
    o.x = 0.5f * (a.x + b.x) * sc.x + sh.x;
    o.y = 0.5f * (a.y + b.y) * sc.y + sh.y;
    o.z = 0.5f * (a.z + b.z) * sc.z + sh.z;
    o.w = 0.5f * (a.w + b.w) * sc.w + sh.w;
    *(float4*)(out + idx * 4) = o;
}

// ---------------- launch ------------------------------------------------------
extern "C" void kernel_launch(void* const* d_in, const int* in_sizes, int n_in,
                              void* d_out, int out_size)
{
    const float* f_atoms = (const float*)d_in[0];
    const float* f_bonds = (const float*)d_in[1];
    const int*   a2b     = (const int*)  d_in[2];
    const int*   b2a     = (const int*)  d_in[3];
    const int*   b2revb  = (const int*)  d_in[4];
    const float* W_i     = (const float*)d_in[5];
    const float* W_h     = (const float*)d_in[6];
    const float* W_o     = (const float*)d_in[7];
    const float* b_o     = (const float*)d_in[8];
    const float* gamma   = (const float*)d_in[9];
    const float* beta    = (const float*)d_in[10];

    float *inp, *msgA, *msgB, *amsg, *hid;
    double *sum, *sumsq;
    __nv_bfloat16 *bi_h, *bi_l, *bh_h, *bh_l, *bo_h, *bo_l;
    cudaGetSymbolAddress((void**)&inp,  g_inp);
    cudaGetSymbolAddress((void**)&msgA, g_msgA);
    cudaGetSymbolAddress((void**)&msgB, g_msgB);
    cudaGetSymbolAddress((void**)&amsg, g_amsg);
    cudaGetSymbolAddress((void**)&hid,  g_hid);
    cudaGetSymbolAddress((void**)&sum,  g_sum);
    cudaGetSymbolAddress((void**)&sumsq,g_sumsq);
    cudaGetSymbolAddress((void**)&bi_h, g_Bi_hi);
    cudaGetSymbolAddress((void**)&bi_l, g_Bi_lo);
    cudaGetSymbolAddress((void**)&bh_h, g_Bh_hi);
    cudaGetSymbolAddress((void**)&bh_l, g_Bh_lo);
    cudaGetSymbolAddress((void**)&bo_h, g_Bo_hi);
    cudaGetSymbolAddress((void**)&bo_l, g_Bo_lo);

    cudaFuncSetAttribute(tc_gemm<0>, cudaFuncAttributeMaxDynamicSharedMemorySize, SMEM_TOTAL);
    cudaFuncSetAttribute(tc_gemm<1>, cudaFuncAttributeMaxDynamicSharedMemorySize, SMEM_TOTAL);
    cudaFuncSetAttribute(tc_gemm<2>, cudaFuncAttributeMaxDynamicSharedMemorySize, SMEM_TOTAL);

    zero_stats<<<1, 1024>>>();
    split_w<<<(320 * 160 + 255) / 256, 256>>>(W_i, BF, 160, bi_h, bi_l);
    split_w<<<(320 * 320 + 255) / 256, 256>>>(W_h, HD, 320, bh_h, bh_l);
    split_w<<<(320 * 448 + 255) / 256, 256>>>(W_o, AF + HD, 448, bo_h, bo_l);

    dim3 gB(1, (NBND + 63) / 64);   // 1 x 6251
    dim3 gO(1, (NATM + 63) / 64);   // 1 x 1563
    const int AGG_G = (NATM * 75 + 255) / 256;

    tc_gemm<0><<<gB, 256, SMEM_TOTAL>>>(f_bonds, bi_h, bi_l, nullptr, nullptr, nullptr,
                                        nullptr, nullptr, nullptr, msgA, inp, NBND);
    agg_kernel<<<AGG_G, 256>>>(msgA, a2b, amsg);
    tc_gemm<1><<<gB, 256, SMEM_TOTAL>>>(nullptr, bh_h, bh_l, inp, amsg, msgA,
                                        b2a, b2revb, nullptr, msgB, nullptr, NBND);
    agg_kernel<<<AGG_G, 256>>>(msgB, a2b, amsg);
    tc_gemm<1><<<gB, 256, SMEM_TOTAL>>>(nullptr, bh_h, bh_l, inp, amsg, msgB,
                                        b2a, b2revb, nullptr, msgA, nullptr, NBND);
    agg_kernel<<<AGG_G, 256>>>(msgA, a2b, amsg);
    tc_gemm<2><<<gO, 256, SMEM_TOTAL>>>(f_atoms, bo_h, bo_l, nullptr, amsg, nullptr,
                                        nullptr, nullptr, b_o, hid, nullptr, NATM);

    stats_kernel<<<(NATM - 1 + 511) / 512, 320>>>(hid + HD, NATM - 1, sum, sumsq);
    stats_und_kernel<<<(NUND - 1 + 511) / 512, 320>>>(msgA, sum + HD, sumsq + HD);
    finalize_stats<<<(2 * HD + 255) / 256, 256>>>(NATM - 1, NUND - 1, gamma, beta);

    float* outp = (float*)d_out;
    long nAtom4 = (long)(NATM - 1) * 75;
    long nBond4 = (long)(NUND - 1) * 75;
    norm_kernel<<<(int)((nAtom4 + 255) / 256), 256>>>(hid + HD, NATM - 1, 0, outp);
    norm_und_kernel<<<(int)((nBond4 + 255) / 256), 256>>>(msgA, outp + nAtom4 * 4);
}

// round 8
// speedup vs baseline: 4.3450x; 1.1471x over previous
#include <cuda_runtime.h>
#include <cuda_bf16.h>
#include <cstdint>
#include <cstddef>

#define NBND 400001
#define NATM 100000
#define HD   300
#define AF   133
#define BF   147
#define MAXNB 6
#define NUND 200001

// ---------------- scratch ---------------------------------------------------
__device__ float g_inp [(size_t)NBND * HD];
__device__ float g_msgA[(size_t)NBND * HD];
__device__ float g_msgB[(size_t)NBND * HD];
__device__ float g_amsg[(size_t)NATM * HD];
__device__ float g_hid [(size_t)NATM * HD];
__device__ double g_sum  [2][HD];
__device__ double g_sumsq[2][HD];
__device__ float g_scale[2][HD];
__device__ float g_shift[2][HD];

// pre-split, pre-transposed weights: g_B[n][kpad] = W[k][n], bf16 hi/lo, zero pad
__device__ __nv_bfloat16 g_Bi_hi[320 * 160], g_Bi_lo[320 * 160];   // W_i K=147 ->160
__device__ __nv_bfloat16 g_Bh_hi[320 * 320], g_Bh_lo[320 * 320];   // W_h K=300 ->320
__device__ __nv_bfloat16 g_Bo_hi[320 * 448], g_Bo_lo[320 * 448];   // W_o K=433 ->448

// ---------------- helpers -----------------------------------------------------
__device__ __forceinline__ void mma16816(float* c, const uint32_t* a,
                                         uint32_t b0, uint32_t b1) {
    asm volatile(
        "mma.sync.aligned.m16n8k16.row.col.f32.bf16.bf16.f32 "
        "{%0,%1,%2,%3}, {%4,%5,%6,%7}, {%8,%9}, {%0,%1,%2,%3};"
        : "+f"(c[0]), "+f"(c[1]), "+f"(c[2]), "+f"(c[3])
        : "r"(a[0]), "r"(a[1]), "r"(a[2]), "r"(a[3]), "r"(b0), "r"(b1));
}
__device__ __forceinline__ uint32_t pack_hi(float x, float y) {
    __nv_bfloat16 hx = __float2bfloat16(x), hy = __float2bfloat16(y);
    return (uint32_t)__bfloat16_as_ushort(hx) | ((uint32_t)__bfloat16_as_ushort(hy) << 16);
}
__device__ __forceinline__ uint32_t pack_lo(float x, float y) {
    __nv_bfloat16 hx = __float2bfloat16(x), hy = __float2bfloat16(y);
    __nv_bfloat16 lx = __float2bfloat16(x - __bfloat162float(hx));
    __nv_bfloat16 ly = __float2bfloat16(y - __bfloat162float(hy));
    return (uint32_t)__bfloat16_as_ushort(lx) | ((uint32_t)__bfloat16_as_ushort(ly) << 16);
}
__device__ __forceinline__ uint32_t smem_u32(const void* p) {
    uint32_t a;
    asm("{ .reg .u64 t; cvta.to.shared.u64 t, %1; cvt.u32.u64 %0, t; }" : "=r"(a) : "l"(p));
    return a;
}
__device__ __forceinline__ void cp16(uint32_t dst, const void* src) {
    asm volatile("cp.async.cg.shared.global [%0], [%1], 16;" :: "r"(dst), "l"(src));
}
__device__ __forceinline__ void cp_commit() {
    asm volatile("cp.async.commit_group;" ::: "memory");
}
__device__ __forceinline__ void cp_wait0() {
    asm volatile("cp.async.wait_group 0;" ::: "memory");
}

// ---------------- HMMA GEMM --------------------------------------------------
// C[M,300] = A[M,K] @ W[K,300]; CTA tile 128x320 (full width), 512 threads,
// warp grid 4m x 4n, warp tile 32x80, BK=32, double-buffered (B via cp.async).
// 3-term bf16 split: AhBh + AhBl + AlBh.
// MODE 0: A = f_bonds (K=147). out = acc  (inp; consumers apply relu)
// MODE 1: A = amsg[b2a[r]] - maybe_relu(msgsrc[b2revb[r]]) (K=300).
//         out = relu(inp + acc)
// MODE 2: A = concat(f_atoms, amsg) (K=433). out = relu(acc + bias)
constexpr int RSA = 80;                 // smem row stride bytes (40 bf16)
constexpr int OFF_AH = 0;               // 128*80 = 10240
constexpr int OFF_AL = 10240;
constexpr int OFF_BH = 20480;           // 320*80 = 25600
constexpr int OFF_BL = 46080;
constexpr int STAGE  = 71680;
constexpr int SMEM_TOTAL = 2 * STAGE;   // 143360

template <int MODE>
__global__ __launch_bounds__(512, 1) void tc_gemm(
    const float* __restrict__ A,
    const __nv_bfloat16* __restrict__ Bhi,
    const __nv_bfloat16* __restrict__ Blo,
    const float* __restrict__ inp,
    const float* __restrict__ amsg,
    const float* __restrict__ msgsrc,
    const int*   __restrict__ b2a,
    const int*   __restrict__ b2revb,
    const float* __restrict__ bias,
    float* __restrict__ out,
    int M, int relu_src)
{
    constexpr int K    = (MODE == 0) ? BF : (MODE == 1) ? HD : (AF + HD);
    constexpr int NC   = (K + 31) / 32;
    constexpr int KPAD = NC * 32;

    extern __shared__ char smem[];
    const uint32_t sbase = smem_u32(smem);
    const int tid = threadIdx.x;
    const int wid = tid >> 5, lid = tid & 31;
    const int wm = wid & 3, wn = wid >> 2;          // 4m x 4n warp grid
    const int grp = lid >> 2, thr = lid & 3;
    const int m0 = blockIdx.x * 128;

    // MODE1 gather pointers (4 threads per row)
    const float4* pa = nullptr; const float4* pb = nullptr;
    int rowvalid = 0;
    const int arow = tid >> 2;                 // 0..127
    const int kq   = (tid & 3) * 8;            // 0,8,16,24
    if (MODE == 1) {
        int gr = m0 + arow;
        rowvalid = (gr < M);
        int ia = rowvalid ? b2a[gr] : 0;
        int ib = rowvalid ? b2revb[gr] : 0;
        pa = (const float4*)(amsg   + (size_t)ia * HD);
        pb = (const float4*)(msgsrc + (size_t)ib * HD);
    }

    float acc[2][10][4];
#pragma unroll
    for (int mf = 0; mf < 2; mf++)
#pragma unroll
        for (int nf = 0; nf < 10; nf++)
#pragma unroll
            for (int q = 0; q < 4; q++) acc[mf][nf][q] = 0.f;

    float fa[8];   // A prefetch registers

    auto issueB = [&](int c, int buf) {
        const int k0 = c * 32;
        const uint32_t sb = sbase + buf * STAGE;
#pragma unroll
        for (int i = 0; i < 5; i++) {
            int idx = tid + i * 512;            // 2560 = 2 x 320 x 4
            int half = (idx >= 1280);
            int j = half ? idx - 1280 : idx;
            int n = j >> 2, g = j & 3;
            const __nv_bfloat16* src = (half ? Blo : Bhi) + (size_t)n * KPAD + k0 + g * 8;
            cp16(sb + (half ? OFF_BL : OFF_BH) + n * RSA + g * 16, src);
        }
    };
    auto loadA = [&](int c) {
        const int k0 = c * 32;
        if (MODE == 1) {
#pragma unroll
            for (int j = 0; j < 2; j++) {
                int k = k0 + kq + j * 4;
                float4 v = {0.f, 0.f, 0.f, 0.f};
                if (rowvalid && k + 3 < HD) {
                    float4 x = pa[k >> 2], y = pb[k >> 2];
                    if (relu_src) {
                        y.x = fmaxf(y.x, 0.f); y.y = fmaxf(y.y, 0.f);
                        y.z = fmaxf(y.z, 0.f); y.w = fmaxf(y.w, 0.f);
                    }
                    v.x = x.x - y.x; v.y = x.y - y.y; v.z = x.z - y.z; v.w = x.w - y.w;
                }
                fa[j * 4 + 0] = v.x; fa[j * 4 + 1] = v.y;
                fa[j * 4 + 2] = v.z; fa[j * 4 + 3] = v.w;
            }
        } else {
#pragma unroll
            for (int i = 0; i < 8; i++) {
                int idx = tid + i * 512;        // 128*32 = 4096
                int r = idx >> 5, kl = idx & 31;
                int gr = m0 + r, k = k0 + kl;
                float v = 0.f;
                if (gr < M) {
                    if (MODE == 0) { if (k < BF) v = A[(size_t)gr * BF + k]; }
                    else {
                        if (k < AF) v = A[(size_t)gr * AF + k];
                        else if (k < AF + HD) v = amsg[(size_t)gr * HD + (k - AF)];
                    }
                }
                fa[i] = v;
            }
        }
    };
    auto storeA = [&](int buf) {
        char* st = smem + buf * STAGE;
        if (MODE == 1) {
            char* dh = st + OFF_AH + arow * RSA + kq * 2;
            char* dl = st + OFF_AL + arow * RSA + kq * 2;
#pragma unroll
            for (int j = 0; j < 4; j++) {
                float x = fa[j * 2], y = fa[j * 2 + 1];
                *(uint32_t*)(dh + j * 4) = pack_hi(x, y);
                *(uint32_t*)(dl + j * 4) = pack_lo(x, y);
            }
        } else {
#pragma unroll
            for (int i = 0; i < 8; i++) {
                int idx = tid + i * 512;
                int r = idx >> 5, kl = idx & 31;
                float v = fa[i];
                __nv_bfloat16 h = __float2bfloat16(v);
                __nv_bfloat16 l = __float2bfloat16(v - __bfloat162float(h));
                *(__nv_bfloat16*)(st + OFF_AH + r * RSA + kl * 2) = h;
                *(__nv_bfloat16*)(st + OFF_AL + r * RSA + kl * 2) = l;
            }
        }
    };

    // prologue
    issueB(0, 0);
    cp_commit();
    loadA(0);
    storeA(0);
    cp_wait0();
    __syncthreads();

    for (int c = 0; c < NC; c++) {
        const int cur = c & 1;
        const bool more = (c + 1 < NC);
        if (more) { issueB(c + 1, cur ^ 1); cp_commit(); loadA(c + 1); }

        const char* st = smem + cur * STAGE;
#pragma unroll
        for (int s = 0; s < 2; s++) {
            const int kb = s * 32 + thr * 4;
            uint32_t ah[2][4], al[2][4];
#pragma unroll
            for (int mf = 0; mf < 2; mf++) {
                int base = (wm * 32 + mf * 16 + grp) * RSA + kb;
                ah[mf][0] = *(const uint32_t*)(st + OFF_AH + base);
                ah[mf][1] = *(const uint32_t*)(st + OFF_AH + base + 8 * RSA);
                ah[mf][2] = *(const uint32_t*)(st + OFF_AH + base + 16);
                ah[mf][3] = *(const uint32_t*)(st + OFF_AH + base + 8 * RSA + 16);
                al[mf][0] = *(const uint32_t*)(st + OFF_AL + base);
                al[mf][1] = *(const uint32_t*)(st + OFF_AL + base + 8 * RSA);
                al[mf][2] = *(const uint32_t*)(st + OFF_AL + base + 16);
                al[mf][3] = *(const uint32_t*)(st + OFF_AL + base + 8 * RSA + 16);
            }
#pragma unroll
            for (int nf = 0; nf < 10; nf++) {
                int bb = (wn * 80 + nf * 8 + grp) * RSA + kb;
                uint32_t bh0 = *(const uint32_t*)(st + OFF_BH + bb);
                uint32_t bh1 = *(const uint32_t*)(st + OFF_BH + bb + 16);
                uint32_t bl0 = *(const uint32_t*)(st + OFF_BL + bb);
                uint32_t bl1 = *(const uint32_t*)(st + OFF_BL + bb + 16);
#pragma unroll
                for (int mf = 0; mf < 2; mf++) {
                    mma16816(acc[mf][nf], ah[mf], bh0, bh1);
                    mma16816(acc[mf][nf], ah[mf], bl0, bl1);
                    mma16816(acc[mf][nf], al[mf], bh0, bh1);
                }
            }
        }
        if (more) storeA(cur ^ 1);
        cp_wait0();
        __syncthreads();
    }

    // ---- epilogue ----
#pragma unroll
    for (int mf = 0; mf < 2; mf++) {
#pragma unroll
        for (int nf = 0; nf < 10; nf++) {
            int col = wn * 80 + nf * 8 + thr * 2;
            if (col >= HD) continue;
            int row0 = m0 + wm * 32 + mf * 16 + grp;
#pragma unroll
            for (int h = 0; h < 2; h++) {
                int r = row0 + h * 8;
                if (r >= M) continue;
                size_t o = (size_t)r * HD + col;
                float vx = acc[mf][nf][h * 2 + 0];
                float vy = acc[mf][nf][h * 2 + 1];
                if (MODE == 0) {
                    *(float2*)(out + o) = make_float2(vx, vy);
                } else if (MODE == 1) {
                    float2 p = *(const float2*)(inp + o);
                    *(float2*)(out + o) = make_float2(fmaxf(p.x + vx, 0.f),
                                                      fmaxf(p.y + vy, 0.f));
                } else {
                    *(float2*)(out + o) = make_float2(fmaxf(vx + bias[col], 0.f),
                                                      fmaxf(vy + bias[col + 1], 0.f));
                }
            }
        }
    }
}

// ---------------- fused prep: zero stats + split/transpose all weights --------
__global__ void prep_kernel(const float* __restrict__ W_i,
                            const float* __restrict__ W_h,
                            const float* __restrict__ W_o)
{
    const int S1 = 320 * 160, S2 = 320 * 320, S3 = 320 * 448;
    int idx = blockIdx.x * blockDim.x + threadIdx.x;
    if (idx < 2 * HD) {
        (&g_sum[0][0])[idx]   = 0.0;
        (&g_sumsq[0][0])[idx] = 0.0;
    }
    int t = idx - 600;
    if (t < 0) return;
    const float* W; __nv_bfloat16 *hi, *lo; int K, kpad;
    if (t < S1)            { W = W_i; hi = g_Bi_hi; lo = g_Bi_lo; K = BF;      kpad = 160; }
    else if (t < S1 + S2)  { t -= S1; W = W_h; hi = g_Bh_hi; lo = g_Bh_lo; K = HD; kpad = 320; }
    else if (t < S1+S2+S3) { t -= S1 + S2; W = W_o; hi = g_Bo_hi; lo = g_Bo_lo; K = AF + HD; kpad = 448; }
    else return;
    int n = t / kpad, k = t % kpad;
    float v = (n < HD && k < K) ? W[(size_t)k * HD + n] : 0.f;
    __nv_bfloat16 h = __float2bfloat16(v);
    hi[t] = h;
    lo[t] = __float2bfloat16(v - __bfloat162float(h));
}

// ---------------- aggregation -------------------------------------------------
__global__ void agg_kernel(const float* __restrict__ msg,
                           const int* __restrict__ a2b,
                           float* __restrict__ amsg, int do_relu)
{
    int idx = blockIdx.x * blockDim.x + threadIdx.x;
    if (idx >= NATM * 75) return;
    int i = idx / 75, k4 = idx % 75;
    float4 s = {0.f, 0.f, 0.f, 0.f};
#pragma unroll
    for (int j = 0; j < MAXNB; j++) {
        int b = __ldg(a2b + i * MAXNB + j);
        float4 v = *(const float4*)(msg + (size_t)b * HD + k4 * 4);
        if (do_relu) {
            v.x = fmaxf(v.x, 0.f); v.y = fmaxf(v.y, 0.f);
            v.z = fmaxf(v.z, 0.f); v.w = fmaxf(v.w, 0.f);
        }
        s.x += v.x; s.y += v.y; s.z += v.z; s.w += v.w;
    }
    *(float4*)(amsg + (size_t)i * HD + k4 * 4) = s;
}

// ---------------- batchnorm (two-pass, fp64 accumulation) ---------------------
__global__ void stats_kernel(const float* __restrict__ x, int rows,
                             double* __restrict__ sum, double* __restrict__ sumsq)
{
    int c = threadIdx.x;
    if (c >= HD) return;
    long r0 = (long)blockIdx.x * 512;
    long r1 = r0 + 512; if (r1 > rows) r1 = rows;
    double s = 0.0, s2 = 0.0;
    for (long r = r0; r < r1; r++) {
        double v = (double)x[(size_t)r * HD + c];
        s += v; s2 += v * v;
    }
    atomicAdd(&sum[c], s);
    atomicAdd(&sumsq[c], s2);
}

__global__ void stats_und_kernel(const float* __restrict__ msg,
                                 double* __restrict__ sum, double* __restrict__ sumsq)
{
    int c = threadIdx.x;
    if (c >= HD) return;
    long r0 = (long)blockIdx.x * 512 + 1;
    long r1 = r0 + 512; if (r1 > NUND) r1 = NUND;
    double s = 0.0, s2 = 0.0;
    for (long r = r0; r < r1; r++) {
        float v = 0.5f * (msg[(size_t)(2 * r) * HD + c] + msg[(size_t)(2 * r - 1) * HD + c]);
        double d = (double)v;
        s += d; s2 += d * d;
    }
    atomicAdd(&sum[c], s);
    atomicAdd(&sumsq[c], s2);
}

__global__ void finalize_stats(int rowsA, int rowsB,
                               const float* __restrict__ gamma,
                               const float* __restrict__ beta)
{
    int t = blockIdx.x * blockDim.x + threadIdx.x;
    if (t >= 2 * HD) return;
    int g = t / HD, c = t % HD;
    long rows = g ? rowsB : rowsA;
    double mu  = g_sum[g][c] / rows;
    double var = g_sumsq[g][c] / rows - mu * mu;
    double sc  = (double)gamma[c] / sqrt(var + 1e-5);
    g_scale[g][c] = (float)sc;
    g_shift[g][c] = beta[c] - (float)(mu * sc);
}

__global__ void norm_kernel(const float* __restrict__ x, long rows, int grp,
                            float* __restrict__ out)
{
    long idx = (long)blockIdx.x * blockDim.x + threadIdx.x;
    if (idx >= rows * 75) return;
    int c4 = (int)(idx % 75);
    float4 v  = *(const float4*)(x + idx * 4);
    float4 sc = *(const float4*)(&g_scale[grp][c4 * 4]);
    float4 sh = *(const float4*)(&g_shift[grp][c4 * 4]);
    float4 o;
    o.x = v.x * sc.x + sh.x; o.y = v.y * sc.y + sh.y;
    o.z = v.z * sc.z + sh.z; o.w = v.w * sc.w + sh.w;
    *(float4*)(out + idx * 4) = o;
}

__global__ void norm_und_kernel(const float* __restrict__ msg, float* __restrict__ out)
{
    long idx = (long)blockIdx.x * blockDim.x + threadIdx.x;
    if (idx >= (long)(NUND - 1) * 75) return;
    long r = idx / 75 + 1;
    int c4 = (int)(idx % 75);
    float4 a = *(const float4*)(msg + (size_t)(2 * r) * HD + c4 * 4);
    float4 b = *(const float4*)(msg + (size_t)(2 * r - 1) * HD + c4 * 4);
    float4 sc = *(const float4*)(&g_scale[1][c4 * 4]);
    float4 sh = *(const float4*)(&g_shift[1][c4 * 4]);
    float4 o;
    o.x = 0.5f * (a.x + b.x) * sc.x + sh.x;
    o.y = 0.5f * (a.y + b.y) * sc.y + sh.y;
    o.z = 0.5f * (a.z + b.z) * sc.z + sh.z;
    o.w = 0.5f * (a.w + b.w) * sc.w + sh.w;
    *(float4*)(out + idx * 4) = o;
}

// ---------------- launch ------------------------------------------------------
extern "C" void kernel_launch(void* const* d_in, const int* in_sizes, int n_in,
                              void* d_out, int out_size)
{
    const float* f_atoms = (const float*)d_in[0];
    const float* f_bonds = (const float*)d_in[1];
    const int*   a2b     = (const int*)  d_in[2];
    const int*   b2a     = (const int*)  d_in[3];
    const int*   b2revb  = (const int*)  d_in[4];
    const float* W_i     = (const float*)d_in[5];
    const float* W_h     = (const float*)d_in[6];
    const float* W_o     = (const float*)d_in[7];
    const float* b_o     = (const float*)d_in[8];
    const float* gamma   = (const float*)d_in[9];
    const float* beta    = (const float*)d_in[10];

    float *inp, *msgA, *msgB, *amsg, *hid;
    double *sum, *sumsq;
    __nv_bfloat16 *bi_h, *bi_l, *bh_h, *bh_l, *bo_h, *bo_l;
    cudaGetSymbolAddress((void**)&inp,  g_inp);
    cudaGetSymbolAddress((void**)&msgA, g_msgA);
    cudaGetSymbolAddress((void**)&msgB, g_msgB);
    cudaGetSymbolAddress((void**)&amsg, g_amsg);
    cudaGetSymbolAddress((void**)&hid,  g_hid);
    cudaGetSymbolAddress((void**)&sum,  g_sum);
    cudaGetSymbolAddress((void**)&sumsq,g_sumsq);
    cudaGetSymbolAddress((void**)&bi_h, g_Bi_hi);
    cudaGetSymbolAddress((void**)&bi_l, g_Bi_lo);
    cudaGetSymbolAddress((void**)&bh_h, g_Bh_hi);
    cudaGetSymbolAddress((void**)&bh_l, g_Bh_lo);
    cudaGetSymbolAddress((void**)&bo_h, g_Bo_hi);
    cudaGetSymbolAddress((void**)&bo_l, g_Bo_lo);

    cudaFuncSetAttribute(tc_gemm<0>, cudaFuncAttributeMaxDynamicSharedMemorySize, SMEM_TOTAL);
    cudaFuncSetAttribute(tc_gemm<1>, cudaFuncAttributeMaxDynamicSharedMemorySize, SMEM_TOTAL);
    cudaFuncSetAttribute(tc_gemm<2>, cudaFuncAttributeMaxDynamicSharedMemorySize, SMEM_TOTAL);

    // launches: 0 prep | 1 gemm0 | 2 agg | 3 gemm1 | 4 agg | 5 gemm1 (ncu -s 5)
    prep_kernel<<<(600 + 320 * (160 + 320 + 448) + 255) / 256, 256>>>(W_i, W_h, W_o);

    dim3 gB((NBND + 127) / 128);   // 3126
    dim3 gO((NATM + 127) / 128);   // 782
    const int AGG_G = (NATM * 75 + 255) / 256;

    tc_gemm<0><<<gB, 512, SMEM_TOTAL>>>(f_bonds, bi_h, bi_l, nullptr, nullptr, nullptr,
                                        nullptr, nullptr, nullptr, inp, NBND, 0);
    agg_kernel<<<AGG_G, 256>>>(inp, a2b, amsg, 1);
    tc_gemm<1><<<gB, 512, SMEM_TOTAL>>>(nullptr, bh_h, bh_l, inp, amsg, inp,
                                        b2a, b2revb, nullptr, msgB, NBND, 1);
    agg_kernel<<<AGG_G, 256>>>(msgB, a2b, amsg, 0);
    tc_gemm<1><<<gB, 512, SMEM_TOTAL>>>(nullptr, bh_h, bh_l, inp, amsg, msgB,
                                        b2a, b2revb, nullptr, msgA, NBND, 0);
    agg_kernel<<<AGG_G, 256>>>(msgA, a2b, amsg, 0);
    tc_gemm<2><<<gO, 512, SMEM_TOTAL>>>(f_atoms, bo_h, bo_l, nullptr, amsg, nullptr,
                                        nullptr, nullptr, b_o, hid, NATM, 0);

    stats_kernel<<<(NATM - 1 + 511) / 512, 320>>>(hid + HD, NATM - 1, sum, sumsq);
    stats_und_kernel<<<(NUND - 1 + 511) / 512, 320>>>(msgA, sum + HD, sumsq + HD);
    finalize_stats<<<(2 * HD + 255) / 256, 256>>>(NATM - 1, NUND - 1, gamma, beta);

    float* outp = (float*)d_out;
    long nAtom4 = (long)(NATM - 1) * 75;
    long nBond4 = (long)(NUND - 1) * 75;
    norm_kernel<<<(int)((nAtom4 + 255) / 256), 256>>>(hid + HD, NATM - 1, 0, outp);
    norm_und_kernel<<<(int)((nBond4 + 255) / 256), 256>>>(msgA, outp + nAtom4 * 4);
}